// round 5
// baseline (speedup 1.0000x reference)
#include <cuda_runtime.h>

// hybrid_position_embedding — FINAL.
//
// The reference ends with softmax over a SINGLETON axis:
//   hmap = hybrid[:, None, :]   # (B, 1, N)
//   out  = softmax(hmap, axis=1)
// For a single-element axis, exp(x - max(x)) / sum == 1.0 exactly; `hybrid`
// is guaranteed finite by its trunc->int32->float32 round-trip, so there is
// no NaN/inf escape. The output is identically 1.0f for all out_size
// elements, independent of the input tensor. Verified rel_err = 0.0 on four
// consecutive benches (R1-R4).
//
// Perf convergence (R1-R4): kernel 3.49-3.74us across grid shapes 256x256 /
// 128x512 / 64x1024, issue <=9%, occ 20-44%, DRAM 0%. The 1MB of stores is
// ~0.1us; measured time is the fixed per-launch ramp (T_ovh ~5000 cyc) plus
// ~1.1us graph-replay dispatch. Wall time bit-identical at 4.608us regardless
// of config => single-launch overhead floor reached. memset-node (can't
// encode 1.0f pattern) and D2D-copy (source needs its own fill launch)
// alternatives rejected.
//
// Config: 256 CTAs x 256 threads, one guard-free STG.128 per thread
// (best-measured kernel time, 3.488us).

__global__ void __launch_bounds__(256) fill_ones_exact(float4* __restrict__ out) {
    out[blockIdx.x * 256 + threadIdx.x] = make_float4(1.0f, 1.0f, 1.0f, 1.0f);
}

__global__ void __launch_bounds__(256) fill_ones_guarded(float* __restrict__ out, int n) {
    int i4 = (blockIdx.x * 256 + threadIdx.x) * 4;
    if (i4 + 3 < n) {
        *reinterpret_cast<float4*>(out + i4) = make_float4(1.0f, 1.0f, 1.0f, 1.0f);
    } else {
        for (int j = i4; j < n; ++j) out[j] = 1.0f;
    }
}

extern "C" void kernel_launch(void* const* d_in, const int* in_sizes, int n_in,
                              void* d_out, int out_size) {
    (void)d_in; (void)in_sizes; (void)n_in;

    // Fast path: out_size divides exactly into 256-thread CTAs of float4
    // stores (true here: 262144 floats = 65536 float4 = 256 CTAs x 256 thr).
    if ((out_size & 3) == 0 && ((out_size >> 2) & 255) == 0) {
        int blocks = (out_size >> 2) >> 8;    // 256
        fill_ones_exact<<<blocks, 256>>>((float4*)d_out);
    } else {
        int n_vec4 = (out_size + 3) >> 2;
        int blocks = (n_vec4 + 255) / 256;
        fill_ones_guarded<<<blocks, 256>>>((float*)d_out, out_size);
    }
}